// round 15
// baseline (speedup 1.0000x reference)
#include <cuda_runtime.h>
#include <cuda_fp16.h>
#include <cstdint>
#include <math.h>

#define NTOK   16384
#define DIMV   768
#define HEADSN 12
#define DHV    64
#define DFFV   2048
#define DEPTHN 8
#define QSTR   2304            // qkv fused row stride (halves)

// ---------------- scratch (device globals: allocation-guard safe) ----------------
__device__ float  g_x  [NTOK*DIMV];
__device__ __half g_tn [NTOK*DIMV];
__device__ float  g_rv [NTOK*DIMV];
__device__ __half g_o  [NTOK*DIMV];
__device__ __half g_qkv[NTOK*QSTR];
__device__ __half g_hg [NTOK*DFFV];
__device__ float  g_gate[NTOK*HEADSN];
__device__ __half g_wt[7077888];    // transposed weights (fp16)
__device__ float  g_wsm[2*HEADSN*DIMV];  // WmixT / WgT (fp32, coalesced)
__device__ float  g_bperm[2*DFFV];  // permuted FF1 bias

// ---------------- small helpers ----------------
__device__ __forceinline__ void cp16(uint32_t s, const void* g) {
    asm volatile("cp.async.cg.shared.global [%0], [%1], 16;" :: "r"(s), "l"(g));
}
__device__ __forceinline__ float ftanh(float x) {
    const float e = __expf(2.f * x);
    return (e - 1.f) / (e + 1.f);
}

// ---------------- transpose: src[R][C] fp32 -> dst[C][R] fp16 ----------------
__global__ void transpose_kernel(const float* __restrict__ src, __half* __restrict__ dst,
                                 int R, int Ccols)
{
    __shared__ float t[32][33];
    const int c0 = blockIdx.x * 32, r0 = blockIdx.y * 32;
    const int x = threadIdx.x, y = threadIdx.y;       // 32 x 8
    #pragma unroll
    for (int i = 0; i < 32; i += 8)
        t[y + i][x] = src[(size_t)(r0 + y + i) * Ccols + c0 + x];
    __syncthreads();
    #pragma unroll
    for (int i = 0; i < 32; i += 8)
        dst[(size_t)(c0 + y + i) * R + r0 + x] = __float2half_rn(t[x][y + i]);
}

// ---------------- batched transpose: Wq/Wk/Wv/Wo [768,768] -> wt slots 0..3 ----------------
__global__ void transpose_qkvo_kernel(const float* __restrict__ Wq,
                                      const float* __restrict__ Wk,
                                      const float* __restrict__ Wv,
                                      const float* __restrict__ Wo,
                                      __half* __restrict__ dst)
{
    __shared__ float t[32][33];
    const float* src = (blockIdx.z == 0) ? Wq : (blockIdx.z == 1) ? Wk
                     : (blockIdx.z == 2) ? Wv : Wo;
    __half* d = dst + (size_t)blockIdx.z * DIMV * DIMV;
    const int c0 = blockIdx.x * 32, r0 = blockIdx.y * 32;
    const int x = threadIdx.x, y = threadIdx.y;
    #pragma unroll
    for (int i = 0; i < 32; i += 8)
        t[y + i][x] = src[(size_t)(r0 + y + i) * DIMV + c0 + x];
    __syncthreads();
    #pragma unroll
    for (int i = 0; i < 32; i += 8)
        d[(size_t)(c0 + y + i) * DIMV + r0 + x] = __float2half_rn(t[x][y + i]);
}

// ---------------- Wmix/Wg [768,12] -> [12,768] fp32 ----------------
__global__ void wsm_transpose_kernel(const float* __restrict__ Wmix,
                                     const float* __restrict__ Wg,
                                     float* __restrict__ dst)
{
    const int j = blockIdx.x;                  // 0..23
    const float* src = (j < HEADSN) ? Wmix : Wg;
    const int col = (j < HEADSN) ? j : (j - HEADSN);
    for (int c = threadIdx.x; c < DIMV; c += 256)
        dst[(size_t)j * DIMV + c] = src[(size_t)c * HEADSN + col];
}

// ---------------- Win [768,4096] -> interleaved winT [4096,768] fp16 ----------------
__global__ void transpose_ffw_kernel(const float* __restrict__ src, __half* __restrict__ dst)
{
    __shared__ float t[32][33];
    const int c0 = blockIdx.x * 32, r0 = blockIdx.y * 32;
    const int x = threadIdx.x, y = threadIdx.y;
    #pragma unroll
    for (int i = 0; i < 32; i += 8)
        t[y + i][x] = src[(size_t)(r0 + y + i) * (2 * DFFV) + c0 + x];
    __syncthreads();
    #pragma unroll
    for (int i = 0; i < 32; i += 8) {
        const int c = c0 + y + i;
        const int np = (c < DFFV) ? (2 * c) : (2 * (c - DFFV) + 1);
        dst[(size_t)np * DIMV + r0 + x] = __float2half_rn(t[x][y + i]);
    }
}

__global__ void biasperm_kernel(const float* __restrict__ b, float* __restrict__ dst)
{
    const int n = blockIdx.x * 256 + threadIdx.x;
    if (n < 2 * DFFV) {
        const int p = n >> 1, s = n & 1;
        dst[n] = b[p + s * DFFV];
    }
}

// ---------------- rmsnorm: 192 threads/row, float4 vectorized ----------------
__global__ void rmsnorm_kernel(const float* __restrict__ in, const float* __restrict__ w,
                               void* __restrict__ out, int ashalf)
{
    __shared__ float red[6];
    __shared__ float snorm;
    const int row = blockIdx.x;
    const int tid = threadIdx.x;           // 192 threads, all active
    const float4 v = ((const float4*)(in + (size_t)row * DIMV))[tid];
    float ss = v.x * v.x + v.y * v.y + v.z * v.z + v.w * v.w;
    #pragma unroll
    for (int o = 16; o; o >>= 1) ss += __shfl_down_sync(0xffffffffu, ss, o);
    if ((tid & 31) == 0) red[tid >> 5] = ss;
    __syncthreads();
    if (tid == 0) {
        float t = 0.f;
        #pragma unroll
        for (int i = 0; i < 6; i++) t += red[i];
        snorm = rsqrtf(t / (float)DIMV + 1e-6f);
    }
    __syncthreads();
    const float sc = snorm;
    const float4 w4 = ((const float4*)w)[tid];
    const float o0 = v.x * sc * w4.x, o1 = v.y * sc * w4.y;
    const float o2 = v.z * sc * w4.z, o3 = v.w * sc * w4.w;
    if (ashalf) {
        __half2 h0 = __floats2half2_rn(o0, o1);
        __half2 h1 = __floats2half2_rn(o2, o3);
        uint2 u;
        u.x = *(const unsigned int*)&h0;
        u.y = *(const unsigned int*)&h1;
        ((uint2*)((__half*)out + (size_t)row * DIMV))[tid] = u;
    } else {
        ((float4*)((float*)out + (size_t)row * DIMV))[tid] = make_float4(o0, o1, o2, o3);
    }
}

// ============================================================================
// fp16 mma.sync GEMM (fp32 accumulate) — persistent-CTA tile scheduler,
// 128x128 CTA tile, 4 warps (2x2), 64x64 warp tile, ldmatrix.x4, BK=32,
// 4-stage cp.async (3 tiles in flight), 2 CTAs/SM, grid = 296 fixed.
// mode 0: fp32 out (+bias)(+res); mode 1: geglu half out; mode 2: plain half out.
// ============================================================================
#define HROW 40
#define T_TILE_H (128 * HROW)
#define STG_BYTES (2 * T_TILE_H * 2)            // 20480 B
#define NSTAGE 4
#define GEMM_SMEM (NSTAGE * STG_BYTES)          // 81920 B
#define GEMM_GRID 296

__global__ void __launch_bounds__(128) gemm_fp16_kernel(
    const __half* __restrict__ A, const __half* __restrict__ Bt,
    void* __restrict__ Cv, const float* __restrict__ bias,
    const float* __restrict__ res, int M, int N, int K, int mode)
{
    extern __shared__ __half smh[];
    const uint32_t smbase = (uint32_t)__cvta_generic_to_shared(smh);
    const int tid = threadIdx.x;
    const int warp = tid >> 5, lane = tid & 31;
    const int wrow = warp >> 1, wcol = warp & 1;   // 2 x 2 warp grid
    const int grp = lane >> 2, qid = lane & 3;

    const int tL = lane >> 3, rL = lane & 7;
    const int arow = (tL & 1) * 8 + rL;
    const int acol = (tL >> 1) * 8;
    const int brow = (tL >> 1) * 8 + rL;
    const int bcol = (tL & 1) * 8;

    const int KT = K >> 5;
    const int nbx = N >> 7;
    const int ntiles = nbx * (M >> 7);

    for (int t = blockIdx.x; t < ntiles; t += GEMM_GRID) {
        const int bx = t % nbx, by = t / nbx;
        const __half* Ab = A  + (size_t)(by * 128) * K;
        const __half* Bb = Bt + (size_t)(bx * 128) * K;

        float acc[4][8][4];
        #pragma unroll
        for (int a = 0; a < 4; a++)
            #pragma unroll
            for (int b = 0; b < 8; b++)
                #pragma unroll
                for (int c = 0; c < 4; c++) acc[a][b][c] = 0.f;

        auto loadTile = [&](int kt, int stg) {
            const uint32_t sA = smbase + stg * STG_BYTES;
            const uint32_t sB = sA + T_TILE_H * 2;
            const int k0 = kt * 32;
            #pragma unroll
            for (int i = 0; i < 4; i++) {
                int idx = tid + i * 128;
                int r = idx >> 2, c8 = (idx & 3) << 3;
                cp16(sA + (uint32_t)(r * HROW + c8) * 2, Ab + (size_t)r * K + k0 + c8);
                cp16(sB + (uint32_t)(r * HROW + c8) * 2, Bb + (size_t)r * K + k0 + c8);
            }
            asm volatile("cp.async.commit_group;");
        };

        auto computeTile = [&](int stg) {
            const uint32_t sA = smbase + stg * STG_BYTES;
            const uint32_t sB = sA + T_TILE_H * 2;
            #pragma unroll
            for (int kk = 0; kk < 2; kk++) {
                const int kb0 = kk * 16;
                uint32_t af[4][4], bf[8][2];
                #pragma unroll
                for (int mt = 0; mt < 4; mt++) {
                    const uint32_t a_ad = sA +
                        (uint32_t)((wrow * 64 + mt * 16 + arow) * HROW + kb0 + acol) * 2;
                    asm volatile(
                        "ldmatrix.sync.aligned.m8n8.x4.shared.b16 {%0,%1,%2,%3}, [%4];"
                        : "=r"(af[mt][0]), "=r"(af[mt][1]), "=r"(af[mt][2]), "=r"(af[mt][3])
                        : "r"(a_ad));
                }
                #pragma unroll
                for (int nt2 = 0; nt2 < 4; nt2++) {
                    const uint32_t b_ad = sB +
                        (uint32_t)((wcol * 64 + nt2 * 16 + brow) * HROW + kb0 + bcol) * 2;
                    asm volatile(
                        "ldmatrix.sync.aligned.m8n8.x4.shared.b16 {%0,%1,%2,%3}, [%4];"
                        : "=r"(bf[2*nt2][0]), "=r"(bf[2*nt2][1]),
                          "=r"(bf[2*nt2+1][0]), "=r"(bf[2*nt2+1][1])
                        : "r"(b_ad));
                }
                #pragma unroll
                for (int mt = 0; mt < 4; mt++)
                    #pragma unroll
                    for (int nt = 0; nt < 8; nt++)
                        asm volatile(
                            "mma.sync.aligned.m16n8k16.row.col.f32.f16.f16.f32 "
                            "{%0,%1,%2,%3}, {%4,%5,%6,%7}, {%8,%9}, {%0,%1,%2,%3};"
                            : "+f"(acc[mt][nt][0]), "+f"(acc[mt][nt][1]),
                              "+f"(acc[mt][nt][2]), "+f"(acc[mt][nt][3])
                            : "r"(af[mt][0]), "r"(af[mt][1]), "r"(af[mt][2]), "r"(af[mt][3]),
                              "r"(bf[nt][0]), "r"(bf[nt][1]));
            }
        };

        // 4-stage pipeline: 3 tiles in flight
        int issued = (KT < 3) ? KT : 3;
        for (int p = 0; p < issued; p++) loadTile(p, p);
        for (int kt = 0; kt < KT; kt++) {
            const int allow = issued - kt - 1;
            if (allow >= 2)      asm volatile("cp.async.wait_group 2;");
            else if (allow == 1) asm volatile("cp.async.wait_group 1;");
            else                 asm volatile("cp.async.wait_group 0;");
            __syncthreads();
            if (issued < KT) { loadTile(issued, issued & 3); issued++; }
            computeTile(kt & 3);
        }

        if (mode == 0) {
            float* C = (float*)Cv;
            #pragma unroll
            for (int mt = 0; mt < 4; mt++) {
                #pragma unroll
                for (int nt = 0; nt < 8; nt++) {
                    const int r0 = by * 128 + wrow * 64 + mt * 16 + grp;
                    const int c0 = bx * 128 + wcol * 64 + nt * 8 + qid * 2;
                    float v0 = acc[mt][nt][0], v1 = acc[mt][nt][1];
                    float v2 = acc[mt][nt][2], v3 = acc[mt][nt][3];
                    if (bias) {
                        const float b0 = bias[c0], b1 = bias[c0 + 1];
                        v0 += b0; v1 += b1; v2 += b0; v3 += b1;
                    }
                    if (res) {
                        const float2 ra = *(const float2*)(res + (size_t)r0 * N + c0);
                        const float2 rb = *(const float2*)(res + (size_t)(r0 + 8) * N + c0);
                        v0 += ra.x; v1 += ra.y; v2 += rb.x; v3 += rb.y;
                    }
                    *(float2*)(C + (size_t)r0 * N + c0)       = make_float2(v0, v1);
                    *(float2*)(C + (size_t)(r0 + 8) * N + c0) = make_float2(v2, v3);
                }
            }
        } else if (mode == 1) {
            __half* C = (__half*)Cv;
            const int NOUT = N >> 1;
            #pragma unroll
            for (int mt = 0; mt < 4; mt++) {
                #pragma unroll
                for (int nt = 0; nt < 8; nt++) {
                    const int r0 = by * 128 + wrow * 64 + mt * 16 + grp;
                    const int c0 = bx * 128 + wcol * 64 + nt * 8 + qid * 2;
                    float v0 = acc[mt][nt][0], v1 = acc[mt][nt][1];
                    float v2 = acc[mt][nt][2], v3 = acc[mt][nt][3];
                    if (bias) {
                        const float b0 = bias[c0], b1 = bias[c0 + 1];
                        v0 += b0; v1 += b1; v2 += b0; v3 += b1;
                    }
                    const float ge1 = 0.5f * v1 * (1.f + erff(v1 * 0.70710678118654752f));
                    const float ge3 = 0.5f * v3 * (1.f + erff(v3 * 0.70710678118654752f));
                    const int p = c0 >> 1;
                    C[(size_t)r0 * NOUT + p]       = __float2half_rn(v0 * ge1);
                    C[(size_t)(r0 + 8) * NOUT + p] = __float2half_rn(v2 * ge3);
                }
            }
        } else {
            __half* C = (__half*)Cv;
            #pragma unroll
            for (int mt = 0; mt < 4; mt++) {
                #pragma unroll
                for (int nt = 0; nt < 8; nt++) {
                    const int r0 = by * 128 + wrow * 64 + mt * 16 + grp;
                    const int c0 = bx * 128 + wcol * 64 + nt * 8 + qid * 2;
                    *(__half2*)(C + (size_t)r0 * N + c0) =
                        __floats2half2_rn(acc[mt][nt][0], acc[mt][nt][1]);
                    *(__half2*)(C + (size_t)(r0 + 8) * N + c0) =
                        __floats2half2_rn(acc[mt][nt][2], acc[mt][nt][3]);
                }
            }
        }
        __syncthreads();   // protect smem before next tile's loads
    }
}

// ---------------- fused mix/gate projections + v-lerp + k-norm (qkv fp16) ----------------
__global__ void mixvk_kernel(const __half* __restrict__ tn,
    const float* __restrict__ Wsm, const float* __restrict__ bmix,
    __half* __restrict__ qkv, const float* __restrict__ rv,
    const float* __restrict__ kgam, float* __restrict__ gate)
{
    __shared__ float row[DIMV];
    __shared__ float smix[HEADSN];
    __shared__ float red[24];
    const int tok = blockIdx.x;
    const int tid = threadIdx.x;           // 0..767
    row[tid] = __half2float(tn[(size_t)tok * DIMV + tid]);
    __syncthreads();

    const int w = tid >> 5, lane = tid & 31;
    {
        const float* Wr = Wsm + (size_t)w * DIMV;
        float s = 0.f;
        for (int c = lane; c < DIMV; c += 32) s += row[c] * Wr[c];
        #pragma unroll
        for (int o = 16; o; o >>= 1) s += __shfl_down_sync(0xffffffffu, s, o);
        if (lane == 0) {
            if (w < HEADSN) {
                s += bmix[w];
                smix[w] = 1.f / (1.f + __expf(-s));
            } else {
                gate[tok * HEADSN + (w - HEADSN)] = 1.f / (1.f + __expf(-s));
            }
        }
    }
    __syncthreads();

    const int h = tid >> 6;
    const size_t base = (size_t)tok * QSTR;
    const float m = smix[h];
    const float vv = __half2float(qkv[base + 1536 + tid]);
    qkv[base + 1536 + tid] =
        __float2half_rn(vv + m * (rv[(size_t)tok * DIMV + tid] - vv));
    const float kk = __half2float(qkv[base + 768 + tid]);
    float ss = kk * kk;
    #pragma unroll
    for (int o = 16; o; o >>= 1) ss += __shfl_down_sync(0xffffffffu, ss, o);
    if ((tid & 31) == 0) red[tid >> 5] = ss;
    __syncthreads();
    float n = sqrtf(red[2 * h] + red[2 * h + 1]);
    n = fmaxf(n, 1e-12f);
    qkv[base + 768 + tid] = __float2half_rn((kk / n) * (kgam[tid] + 1.f) * 8.0f);
}

// ---------------- spatial attention: qkv fp16 in, fp32 smem compute ----------------
__global__ void __launch_bounds__(256) attn_spatial_kernel(
    const __half* __restrict__ qkv, const float* __restrict__ gate, __half* __restrict__ o)
{
    extern __shared__ float sm[];
    float* Ks = sm;                 // 256*64
    float* Vs = sm + 256 * 64;
    float* Qs = sm + 2 * 256 * 64;
    const int h  = blockIdx.x;
    const size_t tok0 = (size_t)blockIdx.y * 256;
    const int tid = threadIdx.x;

    #pragma unroll
    for (int it = 0; it < 16; it++) {
        const int idx = tid + it * 256;
        const int row = idx >> 4;
        const int d4  = idx & 15;
        const size_t g4 = (tok0 + row) * (QSTR / 4) + h * 16 + d4;   // uint2 units
        const uint2 uq = ((const uint2*)qkv)[g4];
        const uint2 uk = ((const uint2*)qkv)[g4 + 192];
        const uint2 uv = ((const uint2*)qkv)[g4 + 384];
        const float2 q0 = __half22float2(*(const __half2*)&uq.x);
        const float2 q1 = __half22float2(*(const __half2*)&uq.y);
        const float2 k0 = __half22float2(*(const __half2*)&uk.x);
        const float2 k1 = __half22float2(*(const __half2*)&uk.y);
        const float2 v0 = __half22float2(*(const __half2*)&uv.x);
        const float2 v1 = __half22float2(*(const __half2*)&uv.y);
        ((float4*)Qs)[row * 16 + d4] = make_float4(q0.x, q0.y, q1.x, q1.y);
        ((float4*)Ks)[row * 16 + d4] = make_float4(k0.x, k0.y, k1.x, k1.y);
        ((float4*)Vs)[row * 16 + d4] = make_float4(v0.x, v0.y, v1.x, v1.y);
    }
    __syncthreads();

    float4 qr4[16];
    #pragma unroll
    for (int d4 = 0; d4 < 16; d4++) qr4[d4] = ((const float4*)(Qs + tid * 64))[d4];

    float mx = -1e30f, sum = 0.f;
    float4 oc4[16];
    #pragma unroll
    for (int d4 = 0; d4 < 16; d4++) oc4[d4] = make_float4(0.f, 0.f, 0.f, 0.f);

    for (int j0 = 0; j0 < 256; j0 += 32) {
        float s[32];
        float cmax = -1e30f;
        #pragma unroll
        for (int jj = 0; jj < 32; jj++) {
            const float4* Kr = (const float4*)(Ks + (j0 + jj) * 64);
            float a = 0.f;
            #pragma unroll
            for (int d4 = 0; d4 < 16; d4++) {
                const float4 k4 = Kr[d4];
                a += qr4[d4].x * k4.x + qr4[d4].y * k4.y
                   + qr4[d4].z * k4.z + qr4[d4].w * k4.w;
            }
            a *= 0.125f;
            a = ftanh(a * 0.02f) * 50.f;
            s[jj] = a;
            cmax = fmaxf(cmax, a);
        }
        const float mnew = fmaxf(mx, cmax);
        const float scale = __expf(mx - mnew);
        sum *= scale;
        #pragma unroll
        for (int d4 = 0; d4 < 16; d4++) {
            oc4[d4].x *= scale; oc4[d4].y *= scale;
            oc4[d4].z *= scale; oc4[d4].w *= scale;
        }
        #pragma unroll
        for (int jj = 0; jj < 32; jj++) {
            const float p = __expf(s[jj] - mnew);
            sum += p;
            const float4* Vr = (const float4*)(Vs + (j0 + jj) * 64);
            #pragma unroll
            for (int d4 = 0; d4 < 16; d4++) {
                const float4 v4 = Vr[d4];
                oc4[d4].x += p * v4.x; oc4[d4].y += p * v4.y;
                oc4[d4].z += p * v4.z; oc4[d4].w += p * v4.w;
            }
        }
        mx = mnew;
    }
    const float inv = 1.f / sum;
    const float g = gate[(tok0 + tid) * HEADSN + h] * inv;
    __half* ob = o + (tok0 + tid) * DIMV + h * DHV;
    #pragma unroll
    for (int d4 = 0; d4 < 16; d4++) {
        __half2 h0 = __floats2half2_rn(oc4[d4].x * g, oc4[d4].y * g);
        __half2 h1 = __floats2half2_rn(oc4[d4].z * g, oc4[d4].w * g);
        uint2 u;
        u.x = *(const unsigned int*)&h0;
        u.y = *(const unsigned int*)&h1;
        ((uint2*)ob)[d4] = u;
    }
}

// ---------------- time attention: seq=32 causal + rotary (qkv fp16) ----------------
__global__ void attn_time_kernel(
    const __half* __restrict__ qkv, const float* __restrict__ gate, __half* __restrict__ o)
{
    __shared__ float Ks[32 * 64];
    __shared__ float Vs[32 * 64];
    const int h  = blockIdx.x;
    const int bs = blockIdx.y;
    const int b = bs >> 8, s = bs & 255;
    const int lane = threadIdx.x;
    const size_t tok = ((size_t)(b * 32 + lane) * 256 + s);
    const size_t base = tok * QSTR + h * DHV;

    float cr[32], sr[32];
    #pragma unroll
    for (int d = 0; d < 32; d++) {
        const float fr = (float)lane * __expf(-(float)d * 0.28782313662425572f);
        cr[d] = __cosf(fr); sr[d] = __sinf(fr);
    }

    {
        float kr[64];
        #pragma unroll
        for (int d = 0; d < 64; d++) {
            kr[d] = __half2float(qkv[base + 768 + d]);
            Vs[lane * 64 + d] = __half2float(qkv[base + 1536 + d]);
        }
        #pragma unroll
        for (int d = 0; d < 32; d++) {
            Ks[lane * 64 + d]      = kr[d]      * cr[d] - kr[d + 32] * sr[d];
            Ks[lane * 64 + d + 32] = kr[d + 32] * cr[d] + kr[d]      * sr[d];
        }
    }
    __syncwarp();

    float qr[64];
    {
        float qt[64];
        #pragma unroll
        for (int d = 0; d < 64; d++) qt[d] = __half2float(qkv[base + d]);
        #pragma unroll
        for (int d = 0; d < 32; d++) {
            qr[d]      = qt[d]      * cr[d] - qt[d + 32] * sr[d];
            qr[d + 32] = qt[d + 32] * cr[d] + qt[d]      * sr[d];
        }
    }

    float sc[32];
    float mx = -1e30f;
    #pragma unroll
    for (int j = 0; j < 32; j++) {
        float a;
        if (j <= lane) {
            a = 0.f;
            #pragma unroll
            for (int d = 0; d < 64; d++) a += qr[d] * Ks[j * 64 + d];
            a *= 0.125f;
            a = ftanh(a * 0.02f) * 50.f;
        } else {
            a = -1e30f;
        }
        sc[j] = a;
        mx = fmaxf(mx, a);
    }
    float sum = 0.f;
    #pragma unroll
    for (int j = 0; j < 32; j++) {
        float e = (j <= lane) ? __expf(sc[j] - mx) : 0.f;
        sc[j] = e; sum += e;
    }
    const float inv = 1.f / sum;

    float oc[64];
    #pragma unroll
    for (int d = 0; d < 64; d++) oc[d] = 0.f;
    #pragma unroll
    for (int j = 0; j < 32; j++) {
        const float p = sc[j] * inv;
        #pragma unroll
        for (int d = 0; d < 64; d++) oc[d] += p * Vs[j * 64 + d];
    }
    const float g = gate[tok * HEADSN + h];
    __half* ob = o + tok * DIMV + h * DHV;
    #pragma unroll
    for (int d = 0; d < 64; d++) ob[d] = __float2half_rn(oc[d] * g);
}

// ---------------- host orchestration ----------------
extern "C" void kernel_launch(void* const* d_in, const int* in_sizes, int n_in,
                              void* d_out, int out_size)
{
    const float* tokens       = (const float*)d_in[0];
    const float* attn_norm_w  = (const float*)d_in[1];
    const float* Wq           = (const float*)d_in[2];
    const float* Wk           = (const float*)d_in[3];
    const float* Wv           = (const float*)d_in[4];
    const float* Wo           = (const float*)d_in[5];
    const float* Wg           = (const float*)d_in[6];
    const float* Wmix         = (const float*)d_in[7];
    const float* bmix         = (const float*)d_in[8];
    const float* kgam         = (const float*)d_in[9];
    const float* ff_norm_w    = (const float*)d_in[10];
    const float* Win          = (const float*)d_in[11];
    const float* b_in         = (const float*)d_in[12];
    const float* Wout         = (const float*)d_in[13];
    const float* b_out        = (const float*)d_in[14];
    const float* vr_norm_w    = (const float*)d_in[15];
    const float* vr_W         = (const float*)d_in[16];
    const float* final_norm_w = (const float*)d_in[17];

    float *x, *rv, *gate, *bperm, *wsm;
    __half *tn, *o, *qkv, *hg, *wt;
    cudaGetSymbolAddress((void**)&x,     g_x);
    cudaGetSymbolAddress((void**)&tn,    g_tn);
    cudaGetSymbolAddress((void**)&rv,    g_rv);
    cudaGetSymbolAddress((void**)&o,     g_o);
    cudaGetSymbolAddress((void**)&qkv,   g_qkv);
    cudaGetSymbolAddress((void**)&hg,    g_hg);
    cudaGetSymbolAddress((void**)&gate,  g_gate);
    cudaGetSymbolAddress((void**)&wt,    g_wt);
    cudaGetSymbolAddress((void**)&wsm,   g_wsm);
    cudaGetSymbolAddress((void**)&bperm, g_bperm);

    __half* wqkvT = wt;                          // [2304, 768]
    __half* woT   = wt + 3 * 589824;             // [768, 768]
    __half* winT  = wt + 4 * 589824;             // [4096, 768] interleaved
    __half* woutT = wt + 4 * 589824 + 3145728;   // [768, 2048]

    const int SPATIAL_SMEM = 3 * 256 * 64 * 4;   // 192 KB
    cudaFuncSetAttribute(attn_spatial_kernel,
                         cudaFuncAttributeMaxDynamicSharedMemorySize, SPATIAL_SMEM);
    cudaFuncSetAttribute(gemm_fp16_kernel,
                         cudaFuncAttributeMaxDynamicSharedMemorySize, GEMM_SMEM);

    const dim3 tb(32, 8);
    auto GEMM = [&](const __half* A, const __half* Bt, void* Cc,
                    const float* bias, const float* res, int M, int N, int K, int mode) {
        gemm_fp16_kernel<<<GEMM_GRID, 128, GEMM_SMEM>>>(A, Bt, Cc, bias, res, M, N, K, mode);
    };

    // prologue
    transpose_kernel<<<dim3(24, 24), tb>>>(vr_W, woT, 768, 768);
    rmsnorm_kernel<<<NTOK, 192>>>(tokens, vr_norm_w, tn, 1);
    GEMM(tn, woT, rv, nullptr, nullptr, NTOK, DIMV, DIMV, 0);

    const float* xcur = tokens;     // layer-0 residual source

    for (int i = 0; i < DEPTHN; i++) {
        const float* wq_i   = Wq   + (size_t)i * DIMV * DIMV;
        const float* wk_i   = Wk   + (size_t)i * DIMV * DIMV;
        const float* wv_i   = Wv   + (size_t)i * DIMV * DIMV;
        const float* wo_i   = Wo   + (size_t)i * DIMV * DIMV;
        const float* wg_i   = Wg   + (size_t)i * DIMV * HEADSN;
        const float* wmix_i = Wmix + (size_t)i * DIMV * HEADSN;
        const float* bmix_i = bmix + (size_t)i * HEADSN;
        const float* kgam_i = kgam + (size_t)i * HEADSN * DHV;
        const float* win_i  = Win  + (size_t)i * DIMV * 2 * DFFV;
        const float* bin_i  = b_in + (size_t)i * 2 * DFFV;
        const float* wout_i = Wout + (size_t)i * DFFV * DIMV;
        const float* bout_i = b_out + (size_t)i * DIMV;

        // attention sublayer
        rmsnorm_kernel<<<NTOK, 192>>>(xcur, attn_norm_w + (size_t)i * DIMV, tn, 1);
        transpose_qkvo_kernel<<<dim3(24, 24, 4), tb>>>(wq_i, wk_i, wv_i, wo_i, wqkvT);
        GEMM(tn, wqkvT, qkv, nullptr, nullptr, NTOK, QSTR, DIMV, 2);
        wsm_transpose_kernel<<<24, 256>>>(wmix_i, wg_i, wsm);
        mixvk_kernel<<<NTOK, 768>>>(tn, wsm, bmix_i, qkv, rv, kgam_i, gate);

        if ((i + 1) % 4 == 0)
            attn_time_kernel<<<dim3(HEADSN, 512), 32>>>(qkv, gate, o);
        else
            attn_spatial_kernel<<<dim3(HEADSN, 64), 256, SPATIAL_SMEM>>>(qkv, gate, o);

        GEMM(o, woT, x, nullptr, xcur, NTOK, DIMV, DIMV, 0);
        xcur = x;

        // feedforward sublayer (geglu fused into FF1 epilogue)
        rmsnorm_kernel<<<NTOK, 192>>>(x, ff_norm_w + (size_t)i * DIMV, tn, 1);
        transpose_ffw_kernel<<<dim3(128, 24), tb>>>(win_i, winT);
        biasperm_kernel<<<16, 256>>>(bin_i, bperm);
        GEMM(tn, winT, hg, bperm, nullptr, NTOK, 2 * DFFV, DIMV, 1);
        transpose_kernel<<<dim3(24, 64), tb>>>(wout_i, woutT, 2048, 768);
        GEMM(hg, woutT, x, bout_i, x, NTOK, DIMV, DFFV, 0);
    }

    rmsnorm_kernel<<<NTOK, 192>>>(x, final_norm_w, d_out, 0);
}

// round 16
// speedup vs baseline: 1.1307x; 1.1307x over previous
#include <cuda_runtime.h>
#include <cuda_fp16.h>
#include <cstdint>
#include <math.h>

#define NTOK   16384
#define DIMV   768
#define HEADSN 12
#define DHV    64
#define DFFV   2048
#define DEPTHN 8
#define QSTR   2304            // qkv fused row stride (halves)

// ---------------- scratch (device globals: allocation-guard safe) ----------------
__device__ float  g_x  [NTOK*DIMV];
__device__ __half g_tn [NTOK*DIMV];
__device__ float  g_rv [NTOK*DIMV];
__device__ __half g_o  [NTOK*DIMV];
__device__ __half g_qkv[NTOK*QSTR];
__device__ __half g_hg [NTOK*DFFV];
__device__ float  g_gate[NTOK*HEADSN];
__device__ __half g_wt[7077888];    // transposed weights (fp16)
__device__ float  g_wsm[2*HEADSN*DIMV];  // WmixT / WgT (fp32, coalesced)
__device__ float  g_bperm[2*DFFV];  // permuted FF1 bias

// ---------------- small helpers ----------------
__device__ __forceinline__ void cp16(uint32_t s, const void* g) {
    asm volatile("cp.async.cg.shared.global [%0], [%1], 16;" :: "r"(s), "l"(g));
}
__device__ __forceinline__ float ftanh(float x) {
    const float e = __expf(2.f * x);
    return (e - 1.f) / (e + 1.f);
}

// ---------------- transpose: src[R][C] fp32 -> dst[C][R] fp16 ----------------
__global__ void transpose_kernel(const float* __restrict__ src, __half* __restrict__ dst,
                                 int R, int Ccols)
{
    __shared__ float t[32][33];
    const int c0 = blockIdx.x * 32, r0 = blockIdx.y * 32;
    const int x = threadIdx.x, y = threadIdx.y;       // 32 x 8
    #pragma unroll
    for (int i = 0; i < 32; i += 8)
        t[y + i][x] = src[(size_t)(r0 + y + i) * Ccols + c0 + x];
    __syncthreads();
    #pragma unroll
    for (int i = 0; i < 32; i += 8)
        dst[(size_t)(c0 + y + i) * R + r0 + x] = __float2half_rn(t[x][y + i]);
}

// ---------------- batched transpose: Wq/Wk/Wv/Wo [768,768] -> wt slots 0..3 ----------------
__global__ void transpose_qkvo_kernel(const float* __restrict__ Wq,
                                      const float* __restrict__ Wk,
                                      const float* __restrict__ Wv,
                                      const float* __restrict__ Wo,
                                      __half* __restrict__ dst)
{
    __shared__ float t[32][33];
    const float* src = (blockIdx.z == 0) ? Wq : (blockIdx.z == 1) ? Wk
                     : (blockIdx.z == 2) ? Wv : Wo;
    __half* d = dst + (size_t)blockIdx.z * DIMV * DIMV;
    const int c0 = blockIdx.x * 32, r0 = blockIdx.y * 32;
    const int x = threadIdx.x, y = threadIdx.y;
    #pragma unroll
    for (int i = 0; i < 32; i += 8)
        t[y + i][x] = src[(size_t)(r0 + y + i) * DIMV + c0 + x];
    __syncthreads();
    #pragma unroll
    for (int i = 0; i < 32; i += 8)
        d[(size_t)(c0 + y + i) * DIMV + r0 + x] = __float2half_rn(t[x][y + i]);
}

// ---------------- per-layer prep: Wmix/Wg -> wsm[24][768]  +  bias permute ----------------
// blocks 0..23: wsm row j; blocks 24..39: bperm chunk of 256
__global__ void layerprep_kernel(const float* __restrict__ Wmix,
                                 const float* __restrict__ Wg,
                                 float* __restrict__ wsm,
                                 const float* __restrict__ b,
                                 float* __restrict__ bperm)
{
    const int j = blockIdx.x;
    if (j < 2 * HEADSN) {
        const float* src = (j < HEADSN) ? Wmix : Wg;
        const int col = (j < HEADSN) ? j : (j - HEADSN);
        for (int c = threadIdx.x; c < DIMV; c += 256)
            wsm[(size_t)j * DIMV + c] = src[(size_t)c * HEADSN + col];
    } else {
        const int n = (j - 2 * HEADSN) * 256 + threadIdx.x;
        const int p = n >> 1, s = n & 1;
        bperm[n] = b[p + s * DFFV];
    }
}

// ---------------- Win [768,4096] -> interleaved winT [4096,768] fp16 ----------------
__global__ void transpose_ffw_kernel(const float* __restrict__ src, __half* __restrict__ dst)
{
    __shared__ float t[32][33];
    const int c0 = blockIdx.x * 32, r0 = blockIdx.y * 32;
    const int x = threadIdx.x, y = threadIdx.y;
    #pragma unroll
    for (int i = 0; i < 32; i += 8)
        t[y + i][x] = src[(size_t)(r0 + y + i) * (2 * DFFV) + c0 + x];
    __syncthreads();
    #pragma unroll
    for (int i = 0; i < 32; i += 8) {
        const int c = c0 + y + i;
        const int np = (c < DFFV) ? (2 * c) : (2 * (c - DFFV) + 1);
        dst[(size_t)np * DIMV + r0 + x] = __float2half_rn(t[x][y + i]);
    }
}

// ---------------- rmsnorm: 192 threads/row, float4 vectorized ----------------
__global__ void rmsnorm_kernel(const float* __restrict__ in, const float* __restrict__ w,
                               void* __restrict__ out, int ashalf)
{
    __shared__ float red[6];
    __shared__ float snorm;
    const int row = blockIdx.x;
    const int tid = threadIdx.x;           // 192 threads, all active
    const float4 v = ((const float4*)(in + (size_t)row * DIMV))[tid];
    float ss = v.x * v.x + v.y * v.y + v.z * v.z + v.w * v.w;
    #pragma unroll
    for (int o = 16; o; o >>= 1) ss += __shfl_down_sync(0xffffffffu, ss, o);
    if ((tid & 31) == 0) red[tid >> 5] = ss;
    __syncthreads();
    if (tid == 0) {
        float t = 0.f;
        #pragma unroll
        for (int i = 0; i < 6; i++) t += red[i];
        snorm = rsqrtf(t / (float)DIMV + 1e-6f);
    }
    __syncthreads();
    const float sc = snorm;
    const float4 w4 = ((const float4*)w)[tid];
    const float o0 = v.x * sc * w4.x, o1 = v.y * sc * w4.y;
    const float o2 = v.z * sc * w4.z, o3 = v.w * sc * w4.w;
    if (ashalf) {
        __half2 h0 = __floats2half2_rn(o0, o1);
        __half2 h1 = __floats2half2_rn(o2, o3);
        uint2 u;
        u.x = *(const unsigned int*)&h0;
        u.y = *(const unsigned int*)&h1;
        ((uint2*)((__half*)out + (size_t)row * DIMV))[tid] = u;
    } else {
        ((float4*)((float*)out + (size_t)row * DIMV))[tid] = make_float4(o0, o1, o2, o3);
    }
}

// ============================================================================
// fp16 mma.sync GEMM (fp32 accumulate) — R14 config (best measured).
// 128x128 CTA tile, 4 warps (2x2), 64x64 warp tile, m16n8k16, ldmatrix.x4,
// BK=32, 3-stage cp.async, one __syncthreads per k-tile, 2 CTAs/SM.
// mode 0: fp32 out (+bias)(+res); mode 1: geglu half out; mode 2: plain half out.
// ============================================================================
#define HROW 40
#define T_TILE_H (128 * HROW)
#define STG_BYTES (2 * T_TILE_H * 2)            // 20480 B
#define GEMM_SMEM (3 * STG_BYTES)               // 61440 B

__global__ void __launch_bounds__(128) gemm_fp16_kernel(
    const __half* __restrict__ A, const __half* __restrict__ Bt,
    void* __restrict__ Cv, const float* __restrict__ bias,
    const float* __restrict__ res, int M, int N, int K, int mode)
{
    extern __shared__ __half smh[];
    const uint32_t smbase = (uint32_t)__cvta_generic_to_shared(smh);
    const int tid = threadIdx.x;
    const int bx = blockIdx.x, by = blockIdx.y;
    const int warp = tid >> 5, lane = tid & 31;
    const int wrow = warp >> 1, wcol = warp & 1;   // 2 x 2 warp grid
    const int grp = lane >> 2, qid = lane & 3;

    const int tL = lane >> 3, rL = lane & 7;
    const int arow = (tL & 1) * 8 + rL;
    const int acol = (tL >> 1) * 8;
    const int brow = (tL >> 1) * 8 + rL;
    const int bcol = (tL & 1) * 8;

    float acc[4][8][4];
    #pragma unroll
    for (int a = 0; a < 4; a++)
        #pragma unroll
        for (int b = 0; b < 8; b++)
            #pragma unroll
            for (int c = 0; c < 4; c++) acc[a][b][c] = 0.f;

    const int KT = K >> 5;
    const __half* Ab = A  + (size_t)(by * 128) * K;
    const __half* Bb = Bt + (size_t)(bx * 128) * K;

    auto loadTile = [&](int kt, int stg) {
        const uint32_t sA = smbase + stg * STG_BYTES;
        const uint32_t sB = sA + T_TILE_H * 2;
        const int k0 = kt * 32;
        #pragma unroll
        for (int i = 0; i < 4; i++) {
            int idx = tid + i * 128;
            int r = idx >> 2, c8 = (idx & 3) << 3;
            cp16(sA + (uint32_t)(r * HROW + c8) * 2, Ab + (size_t)r * K + k0 + c8);
            cp16(sB + (uint32_t)(r * HROW + c8) * 2, Bb + (size_t)r * K + k0 + c8);
        }
        asm volatile("cp.async.commit_group;");
    };

    auto computeTile = [&](int stg) {
        const uint32_t sA = smbase + stg * STG_BYTES;
        const uint32_t sB = sA + T_TILE_H * 2;
        #pragma unroll
        for (int kk = 0; kk < 2; kk++) {
            const int kb0 = kk * 16;
            uint32_t af[4][4], bf[8][2];
            #pragma unroll
            for (int mt = 0; mt < 4; mt++) {
                const uint32_t a_ad = sA +
                    (uint32_t)((wrow * 64 + mt * 16 + arow) * HROW + kb0 + acol) * 2;
                asm volatile(
                    "ldmatrix.sync.aligned.m8n8.x4.shared.b16 {%0,%1,%2,%3}, [%4];"
                    : "=r"(af[mt][0]), "=r"(af[mt][1]), "=r"(af[mt][2]), "=r"(af[mt][3])
                    : "r"(a_ad));
            }
            #pragma unroll
            for (int nt2 = 0; nt2 < 4; nt2++) {
                const uint32_t b_ad = sB +
                    (uint32_t)((wcol * 64 + nt2 * 16 + brow) * HROW + kb0 + bcol) * 2;
                asm volatile(
                    "ldmatrix.sync.aligned.m8n8.x4.shared.b16 {%0,%1,%2,%3}, [%4];"
                    : "=r"(bf[2*nt2][0]), "=r"(bf[2*nt2][1]),
                      "=r"(bf[2*nt2+1][0]), "=r"(bf[2*nt2+1][1])
                    : "r"(b_ad));
            }
            #pragma unroll
            for (int mt = 0; mt < 4; mt++)
                #pragma unroll
                for (int nt = 0; nt < 8; nt++)
                    asm volatile(
                        "mma.sync.aligned.m16n8k16.row.col.f32.f16.f16.f32 "
                        "{%0,%1,%2,%3}, {%4,%5,%6,%7}, {%8,%9}, {%0,%1,%2,%3};"
                        : "+f"(acc[mt][nt][0]), "+f"(acc[mt][nt][1]),
                          "+f"(acc[mt][nt][2]), "+f"(acc[mt][nt][3])
                        : "r"(af[mt][0]), "r"(af[mt][1]), "r"(af[mt][2]), "r"(af[mt][3]),
                          "r"(bf[nt][0]), "r"(bf[nt][1]));
        }
    };

    loadTile(0, 0);
    loadTile(1, 1);
    for (int kt = 0; kt < KT; kt++) {
        if (kt == KT - 1) asm volatile("cp.async.wait_group 0;");
        else              asm volatile("cp.async.wait_group 1;");
        __syncthreads();
        if (kt + 2 < KT) loadTile(kt + 2, (kt + 2) % 3);
        computeTile(kt % 3);
    }

    if (mode == 0) {
        float* C = (float*)Cv;
        #pragma unroll
        for (int mt = 0; mt < 4; mt++) {
            #pragma unroll
            for (int nt = 0; nt < 8; nt++) {
                const int r0 = by * 128 + wrow * 64 + mt * 16 + grp;
                const int c0 = bx * 128 + wcol * 64 + nt * 8 + qid * 2;
                float v0 = acc[mt][nt][0], v1 = acc[mt][nt][1];
                float v2 = acc[mt][nt][2], v3 = acc[mt][nt][3];
                if (bias) {
                    const float b0 = bias[c0], b1 = bias[c0 + 1];
                    v0 += b0; v1 += b1; v2 += b0; v3 += b1;
                }
                if (res) {
                    const float2 ra = *(const float2*)(res + (size_t)r0 * N + c0);
                    const float2 rb = *(const float2*)(res + (size_t)(r0 + 8) * N + c0);
                    v0 += ra.x; v1 += ra.y; v2 += rb.x; v3 += rb.y;
                }
                *(float2*)(C + (size_t)r0 * N + c0)       = make_float2(v0, v1);
                *(float2*)(C + (size_t)(r0 + 8) * N + c0) = make_float2(v2, v3);
            }
        }
    } else if (mode == 1) {
        __half* C = (__half*)Cv;
        const int NOUT = N >> 1;
        #pragma unroll
        for (int mt = 0; mt < 4; mt++) {
            #pragma unroll
            for (int nt = 0; nt < 8; nt++) {
                const int r0 = by * 128 + wrow * 64 + mt * 16 + grp;
                const int c0 = bx * 128 + wcol * 64 + nt * 8 + qid * 2;
                float v0 = acc[mt][nt][0], v1 = acc[mt][nt][1];
                float v2 = acc[mt][nt][2], v3 = acc[mt][nt][3];
                if (bias) {
                    const float b0 = bias[c0], b1 = bias[c0 + 1];
                    v0 += b0; v1 += b1; v2 += b0; v3 += b1;
                }
                const float ge1 = 0.5f * v1 * (1.f + erff(v1 * 0.70710678118654752f));
                const float ge3 = 0.5f * v3 * (1.f + erff(v3 * 0.70710678118654752f));
                const int p = c0 >> 1;
                C[(size_t)r0 * NOUT + p]       = __float2half_rn(v0 * ge1);
                C[(size_t)(r0 + 8) * NOUT + p] = __float2half_rn(v2 * ge3);
            }
        }
    } else {
        __half* C = (__half*)Cv;
        #pragma unroll
        for (int mt = 0; mt < 4; mt++) {
            #pragma unroll
            for (int nt = 0; nt < 8; nt++) {
                const int r0 = by * 128 + wrow * 64 + mt * 16 + grp;
                const int c0 = bx * 128 + wcol * 64 + nt * 8 + qid * 2;
                *(__half2*)(C + (size_t)r0 * N + c0) =
                    __floats2half2_rn(acc[mt][nt][0], acc[mt][nt][1]);
                *(__half2*)(C + (size_t)(r0 + 8) * N + c0) =
                    __floats2half2_rn(acc[mt][nt][2], acc[mt][nt][3]);
            }
        }
    }
}

// ---------------- fused mix/gate projections + v-lerp + k-norm (qkv fp16) ----------------
__global__ void mixvk_kernel(const __half* __restrict__ tn,
    const float* __restrict__ Wsm, const float* __restrict__ bmix,
    __half* __restrict__ qkv, const float* __restrict__ rv,
    const float* __restrict__ kgam, float* __restrict__ gate)
{
    __shared__ float row[DIMV];
    __shared__ float smix[HEADSN];
    __shared__ float red[24];
    const int tok = blockIdx.x;
    const int tid = threadIdx.x;           // 0..767
    row[tid] = __half2float(tn[(size_t)tok * DIMV + tid]);
    __syncthreads();

    const int w = tid >> 5, lane = tid & 31;
    {
        const float* Wr = Wsm + (size_t)w * DIMV;
        float s = 0.f;
        for (int c = lane; c < DIMV; c += 32) s += row[c] * Wr[c];
        #pragma unroll
        for (int o = 16; o; o >>= 1) s += __shfl_down_sync(0xffffffffu, s, o);
        if (lane == 0) {
            if (w < HEADSN) {
                s += bmix[w];
                smix[w] = 1.f / (1.f + __expf(-s));
            } else {
                gate[tok * HEADSN + (w - HEADSN)] = 1.f / (1.f + __expf(-s));
            }
        }
    }
    __syncthreads();

    const int h = tid >> 6;
    const size_t base = (size_t)tok * QSTR;
    const float m = smix[h];
    const float vv = __half2float(qkv[base + 1536 + tid]);
    qkv[base + 1536 + tid] =
        __float2half_rn(vv + m * (rv[(size_t)tok * DIMV + tid] - vv));
    const float kk = __half2float(qkv[base + 768 + tid]);
    float ss = kk * kk;
    #pragma unroll
    for (int o = 16; o; o >>= 1) ss += __shfl_down_sync(0xffffffffu, ss, o);
    if ((tid & 31) == 0) red[tid >> 5] = ss;
    __syncthreads();
    float n = sqrtf(red[2 * h] + red[2 * h + 1]);
    n = fmaxf(n, 1e-12f);
    qkv[base + 768 + tid] = __float2half_rn((kk / n) * (kgam[tid] + 1.f) * 8.0f);
}

// ---------------- spatial attention: qkv fp16 in, fp32 smem compute ----------------
__global__ void __launch_bounds__(256) attn_spatial_kernel(
    const __half* __restrict__ qkv, const float* __restrict__ gate, __half* __restrict__ o)
{
    extern __shared__ float sm[];
    float* Ks = sm;                 // 256*64
    float* Vs = sm + 256 * 64;
    float* Qs = sm + 2 * 256 * 64;
    const int h  = blockIdx.x;
    const size_t tok0 = (size_t)blockIdx.y * 256;
    const int tid = threadIdx.x;

    #pragma unroll
    for (int it = 0; it < 16; it++) {
        const int idx = tid + it * 256;
        const int row = idx >> 4;
        const int d4  = idx & 15;
        const size_t g4 = (tok0 + row) * (QSTR / 4) + h * 16 + d4;   // uint2 units
        const uint2 uq = ((const uint2*)qkv)[g4];
        const uint2 uk = ((const uint2*)qkv)[g4 + 192];
        const uint2 uv = ((const uint2*)qkv)[g4 + 384];
        const float2 q0 = __half22float2(*(const __half2*)&uq.x);
        const float2 q1 = __half22float2(*(const __half2*)&uq.y);
        const float2 k0 = __half22float2(*(const __half2*)&uk.x);
        const float2 k1 = __half22float2(*(const __half2*)&uk.y);
        const float2 v0 = __half22float2(*(const __half2*)&uv.x);
        const float2 v1 = __half22float2(*(const __half2*)&uv.y);
        ((float4*)Qs)[row * 16 + d4] = make_float4(q0.x, q0.y, q1.x, q1.y);
        ((float4*)Ks)[row * 16 + d4] = make_float4(k0.x, k0.y, k1.x, k1.y);
        ((float4*)Vs)[row * 16 + d4] = make_float4(v0.x, v0.y, v1.x, v1.y);
    }
    __syncthreads();

    float4 qr4[16];
    #pragma unroll
    for (int d4 = 0; d4 < 16; d4++) qr4[d4] = ((const float4*)(Qs + tid * 64))[d4];

    float mx = -1e30f, sum = 0.f;
    float4 oc4[16];
    #pragma unroll
    for (int d4 = 0; d4 < 16; d4++) oc4[d4] = make_float4(0.f, 0.f, 0.f, 0.f);

    for (int j0 = 0; j0 < 256; j0 += 32) {
        float s[32];
        float cmax = -1e30f;
        #pragma unroll
        for (int jj = 0; jj < 32; jj++) {
            const float4* Kr = (const float4*)(Ks + (j0 + jj) * 64);
            float a = 0.f;
            #pragma unroll
            for (int d4 = 0; d4 < 16; d4++) {
                const float4 k4 = Kr[d4];
                a += qr4[d4].x * k4.x + qr4[d4].y * k4.y
                   + qr4[d4].z * k4.z + qr4[d4].w * k4.w;
            }
            a *= 0.125f;
            a = ftanh(a * 0.02f) * 50.f;
            s[jj] = a;
            cmax = fmaxf(cmax, a);
        }
        const float mnew = fmaxf(mx, cmax);
        const float scale = __expf(mx - mnew);
        sum *= scale;
        #pragma unroll
        for (int d4 = 0; d4 < 16; d4++) {
            oc4[d4].x *= scale; oc4[d4].y *= scale;
            oc4[d4].z *= scale; oc4[d4].w *= scale;
        }
        #pragma unroll
        for (int jj = 0; jj < 32; jj++) {
            const float p = __expf(s[jj] - mnew);
            sum += p;
            const float4* Vr = (const float4*)(Vs + (j0 + jj) * 64);
            #pragma unroll
            for (int d4 = 0; d4 < 16; d4++) {
                const float4 v4 = Vr[d4];
                oc4[d4].x += p * v4.x; oc4[d4].y += p * v4.y;
                oc4[d4].z += p * v4.z; oc4[d4].w += p * v4.w;
            }
        }
        mx = mnew;
    }
    const float inv = 1.f / sum;
    const float g = gate[(tok0 + tid) * HEADSN + h] * inv;
    __half* ob = o + (tok0 + tid) * DIMV + h * DHV;
    #pragma unroll
    for (int d4 = 0; d4 < 16; d4++) {
        __half2 h0 = __floats2half2_rn(oc4[d4].x * g, oc4[d4].y * g);
        __half2 h1 = __floats2half2_rn(oc4[d4].z * g, oc4[d4].w * g);
        uint2 u;
        u.x = *(const unsigned int*)&h0;
        u.y = *(const unsigned int*)&h1;
        ((uint2*)ob)[d4] = u;
    }
}

// ---------------- time attention: seq=32 causal + rotary (qkv fp16) ----------------
__global__ void attn_time_kernel(
    const __half* __restrict__ qkv, const float* __restrict__ gate, __half* __restrict__ o)
{
    __shared__ float Ks[32 * 64];
    __shared__ float Vs[32 * 64];
    const int h  = blockIdx.x;
    const int bs = blockIdx.y;
    const int b = bs >> 8, s = bs & 255;
    const int lane = threadIdx.x;
    const size_t tok = ((size_t)(b * 32 + lane) * 256 + s);
    const size_t base = tok * QSTR + h * DHV;

    float cr[32], sr[32];
    #pragma unroll
    for (int d = 0; d < 32; d++) {
        const float fr = (float)lane * __expf(-(float)d * 0.28782313662425572f);
        cr[d] = __cosf(fr); sr[d] = __sinf(fr);
    }

    {
        float kr[64];
        #pragma unroll
        for (int d = 0; d < 64; d++) {
            kr[d] = __half2float(qkv[base + 768 + d]);
            Vs[lane * 64 + d] = __half2float(qkv[base + 1536 + d]);
        }
        #pragma unroll
        for (int d = 0; d < 32; d++) {
            Ks[lane * 64 + d]      = kr[d]      * cr[d] - kr[d + 32] * sr[d];
            Ks[lane * 64 + d + 32] = kr[d + 32] * cr[d] + kr[d]      * sr[d];
        }
    }
    __syncwarp();

    float qr[64];
    {
        float qt[64];
        #pragma unroll
        for (int d = 0; d < 64; d++) qt[d] = __half2float(qkv[base + d]);
        #pragma unroll
        for (int d = 0; d < 32; d++) {
            qr[d]      = qt[d]      * cr[d] - qt[d + 32] * sr[d];
            qr[d + 32] = qt[d + 32] * cr[d] + qt[d]      * sr[d];
        }
    }

    float sc[32];
    float mx = -1e30f;
    #pragma unroll
    for (int j = 0; j < 32; j++) {
        float a;
        if (j <= lane) {
            a = 0.f;
            #pragma unroll
            for (int d = 0; d < 64; d++) a += qr[d] * Ks[j * 64 + d];
            a *= 0.125f;
            a = ftanh(a * 0.02f) * 50.f;
        } else {
            a = -1e30f;
        }
        sc[j] = a;
        mx = fmaxf(mx, a);
    }
    float sum = 0.f;
    #pragma unroll
    for (int j = 0; j < 32; j++) {
        float e = (j <= lane) ? __expf(sc[j] - mx) : 0.f;
        sc[j] = e; sum += e;
    }
    const float inv = 1.f / sum;

    float oc[64];
    #pragma unroll
    for (int d = 0; d < 64; d++) oc[d] = 0.f;
    #pragma unroll
    for (int j = 0; j < 32; j++) {
        const float p = sc[j] * inv;
        #pragma unroll
        for (int d = 0; d < 64; d++) oc[d] += p * Vs[j * 64 + d];
    }
    const float g = gate[tok * HEADSN + h];
    __half* ob = o + tok * DIMV + h * DHV;
    #pragma unroll
    for (int d = 0; d < 64; d++) ob[d] = __float2half_rn(oc[d] * g);
}

// ---------------- host orchestration ----------------
extern "C" void kernel_launch(void* const* d_in, const int* in_sizes, int n_in,
                              void* d_out, int out_size)
{
    const float* tokens       = (const float*)d_in[0];
    const float* attn_norm_w  = (const float*)d_in[1];
    const float* Wq           = (const float*)d_in[2];
    const float* Wk           = (const float*)d_in[3];
    const float* Wv           = (const float*)d_in[4];
    const float* Wo           = (const float*)d_in[5];
    const float* Wg           = (const float*)d_in[6];
    const float* Wmix         = (const float*)d_in[7];
    const float* bmix         = (const float*)d_in[8];
    const float* kgam         = (const float*)d_in[9];
    const float* ff_norm_w    = (const float*)d_in[10];
    const float* Win          = (const float*)d_in[11];
    const float* b_in         = (const float*)d_in[12];
    const float* Wout         = (const float*)d_in[13];
    const float* b_out        = (const float*)d_in[14];
    const float* vr_norm_w    = (const float*)d_in[15];
    const float* vr_W         = (const float*)d_in[16];
    const float* final_norm_w = (const float*)d_in[17];

    float *x, *rv, *gate, *bperm, *wsm;
    __half *tn, *o, *qkv, *hg, *wt;
    cudaGetSymbolAddress((void**)&x,     g_x);
    cudaGetSymbolAddress((void**)&tn,    g_tn);
    cudaGetSymbolAddress((void**)&rv,    g_rv);
    cudaGetSymbolAddress((void**)&o,     g_o);
    cudaGetSymbolAddress((void**)&qkv,   g_qkv);
    cudaGetSymbolAddress((void**)&hg,    g_hg);
    cudaGetSymbolAddress((void**)&gate,  g_gate);
    cudaGetSymbolAddress((void**)&wt,    g_wt);
    cudaGetSymbolAddress((void**)&wsm,   g_wsm);
    cudaGetSymbolAddress((void**)&bperm, g_bperm);

    __half* wqkvT = wt;                          // [2304, 768]
    __half* woT   = wt + 3 * 589824;             // [768, 768]
    __half* winT  = wt + 4 * 589824;             // [4096, 768] interleaved
    __half* woutT = wt + 4 * 589824 + 3145728;   // [768, 2048]

    const int SPATIAL_SMEM = 3 * 256 * 64 * 4;   // 192 KB
    cudaFuncSetAttribute(attn_spatial_kernel,
                         cudaFuncAttributeMaxDynamicSharedMemorySize, SPATIAL_SMEM);
    cudaFuncSetAttribute(gemm_fp16_kernel,
                         cudaFuncAttributeMaxDynamicSharedMemorySize, GEMM_SMEM);

    const dim3 tb(32, 8);
    auto GEMM = [&](const __half* A, const __half* Bt, void* Cc,
                    const float* bias, const float* res, int M, int N, int K, int mode) {
        gemm_fp16_kernel<<<dim3(N / 128, M / 128), 128, GEMM_SMEM>>>(A, Bt, Cc, bias, res, M, N, K, mode);
    };

    // prologue
    transpose_kernel<<<dim3(24, 24), tb>>>(vr_W, woT, 768, 768);
    rmsnorm_kernel<<<NTOK, 192>>>(tokens, vr_norm_w, tn, 1);
    GEMM(tn, woT, rv, nullptr, nullptr, NTOK, DIMV, DIMV, 0);

    const float* xcur = tokens;     // layer-0 residual source

    for (int i = 0; i < DEPTHN; i++) {
        const float* wq_i   = Wq   + (size_t)i * DIMV * DIMV;
        const float* wk_i   = Wk   + (size_t)i * DIMV * DIMV;
        const float* wv_i   = Wv   + (size_t)i * DIMV * DIMV;
        const float* wo_i   = Wo   + (size_t)i * DIMV * DIMV;
        const float* wg_i   = Wg   + (size_t)i * DIMV * HEADSN;
        const float* wmix_i = Wmix + (size_t)i * DIMV * HEADSN;
        const float* bmix_i = bmix + (size_t)i * HEADSN;
        const float* kgam_i = kgam + (size_t)i * HEADSN * DHV;
        const float* win_i  = Win  + (size_t)i * DIMV * 2 * DFFV;
        const float* bin_i  = b_in + (size_t)i * 2 * DFFV;
        const float* wout_i = Wout + (size_t)i * DFFV * DIMV;
        const float* bout_i = b_out + (size_t)i * DIMV;

        // attention sublayer
        rmsnorm_kernel<<<NTOK, 192>>>(xcur, attn_norm_w + (size_t)i * DIMV, tn, 1);
        transpose_qkvo_kernel<<<dim3(24, 24, 4), tb>>>(wq_i, wk_i, wv_i, wo_i, wqkvT);
        GEMM(tn, wqkvT, qkv, nullptr, nullptr, NTOK, QSTR, DIMV, 2);
        layerprep_kernel<<<40, 256>>>(wmix_i, wg_i, wsm, bin_i, bperm);
        mixvk_kernel<<<NTOK, 768>>>(tn, wsm, bmix_i, qkv, rv, kgam_i, gate);

        if ((i + 1) % 4 == 0)
            attn_time_kernel<<<dim3(HEADSN, 512), 32>>>(qkv, gate, o);
        else
            attn_spatial_kernel<<<dim3(HEADSN, 64), 256, SPATIAL_SMEM>>>(qkv, gate, o);

        GEMM(o, woT, x, nullptr, xcur, NTOK, DIMV, DIMV, 0);
        xcur = x;

        // feedforward sublayer (geglu fused into FF1 epilogue)
        rmsnorm_kernel<<<NTOK, 192>>>(x, ff_norm_w + (size_t)i * DIMV, tn, 1);
        transpose_ffw_kernel<<<dim3(128, 24), tb>>>(win_i, winT);
        GEMM(tn, winT, hg, bperm, nullptr, NTOK, 2 * DFFV, DIMV, 1);
        transpose_kernel<<<dim3(24, 64), tb>>>(wout_i, woutT, 2048, 768);
        GEMM(hg, woutT, x, bout_i, x, NTOK, DIMV, DFFV, 0);
    }

    rmsnorm_kernel<<<NTOK, 192>>>(x, final_norm_w, d_out, 0);
}

// round 17
// speedup vs baseline: 1.1370x; 1.0055x over previous
#include <cuda_runtime.h>
#include <cuda_fp16.h>
#include <cstdint>
#include <math.h>

#define NTOK   16384
#define DIMV   768
#define HEADSN 12
#define DHV    64
#define DFFV   2048
#define DEPTHN 8
#define QSTR   2304            // qkv fused row stride (halves)
#define WT_LAYER 7077888       // halves per layer: 4*589824 + 3145728 + 1572864

// ---------------- scratch (device globals: allocation-guard safe) ----------------
__device__ float  g_x  [NTOK*DIMV];
__device__ __half g_tn [NTOK*DIMV];
__device__ float  g_rv [NTOK*DIMV];
__device__ __half g_o  [NTOK*DIMV];
__device__ __half g_qkv[NTOK*QSTR];
__device__ __half g_hg [NTOK*DFFV];
__device__ float  g_gate[NTOK*HEADSN];
__device__ __half g_wtall[DEPTHN*WT_LAYER];   // all layers' transposed weights (113 MB)
__device__ __half g_wvr[DIMV*DIMV];           // vr_W^T
__device__ float  g_wsmall[DEPTHN*2*HEADSN*DIMV];
__device__ float  g_bpermall[DEPTHN*2*DFFV];

// ---------------- small helpers ----------------
__device__ __forceinline__ void cp16(uint32_t s, const void* g) {
    asm volatile("cp.async.cg.shared.global [%0], [%1], 16;" :: "r"(s), "l"(g));
}
__device__ __forceinline__ float ftanh(float x) {
    const float e = __expf(2.f * x);
    return (e - 1.f) / (e + 1.f);
}

// ---------------- batched transpose: all layers' Wq/Wk/Wv/Wo -> wtall slots ----------------
__global__ void transpose_qkvo_all(const float* __restrict__ Wq,
                                   const float* __restrict__ Wk,
                                   const float* __restrict__ Wv,
                                   const float* __restrict__ Wo,
                                   __half* __restrict__ dst)
{
    __shared__ float t[32][33];
    const int z = blockIdx.z;                  // 0..4*DEPTHN-1
    const int layer = z >> 2, which = z & 3;
    const float* src = ((which == 0) ? Wq : (which == 1) ? Wk
                      : (which == 2) ? Wv : Wo) + (size_t)layer * DIMV * DIMV;
    __half* d = dst + (size_t)layer * WT_LAYER + (size_t)which * 589824;
    const int c0 = blockIdx.x * 32, r0 = blockIdx.y * 32;
    const int x = threadIdx.x, y = threadIdx.y;
    #pragma unroll
    for (int i = 0; i < 32; i += 8)
        t[y + i][x] = src[(size_t)(r0 + y + i) * DIMV + c0 + x];
    __syncthreads();
    #pragma unroll
    for (int i = 0; i < 32; i += 8)
        d[(size_t)(c0 + y + i) * DIMV + r0 + x] = __float2half_rn(t[x][y + i]);
}

// ---------------- vr_W [768,768] -> g_wvr ----------------
__global__ void transpose_vr_kernel(const float* __restrict__ src, __half* __restrict__ dst)
{
    __shared__ float t[32][33];
    const int c0 = blockIdx.x * 32, r0 = blockIdx.y * 32;
    const int x = threadIdx.x, y = threadIdx.y;
    #pragma unroll
    for (int i = 0; i < 32; i += 8)
        t[y + i][x] = src[(size_t)(r0 + y + i) * DIMV + c0 + x];
    __syncthreads();
    #pragma unroll
    for (int i = 0; i < 32; i += 8)
        dst[(size_t)(c0 + y + i) * DIMV + r0 + x] = __float2half_rn(t[x][y + i]);
}

// ---------------- all layers' Win [768,4096] -> interleaved winT [4096,768] ----------------
__global__ void transpose_ffw_all(const float* __restrict__ Win, __half* __restrict__ dst)
{
    __shared__ float t[32][33];
    const int layer = blockIdx.z;
    const float* src = Win + (size_t)layer * DIMV * 2 * DFFV;
    __half* d = dst + (size_t)layer * WT_LAYER + 4 * 589824;
    const int c0 = blockIdx.x * 32, r0 = blockIdx.y * 32;
    const int x = threadIdx.x, y = threadIdx.y;
    #pragma unroll
    for (int i = 0; i < 32; i += 8)
        t[y + i][x] = src[(size_t)(r0 + y + i) * (2 * DFFV) + c0 + x];
    __syncthreads();
    #pragma unroll
    for (int i = 0; i < 32; i += 8) {
        const int c = c0 + y + i;
        const int np = (c < DFFV) ? (2 * c) : (2 * (c - DFFV) + 1);
        d[(size_t)np * DIMV + r0 + x] = __float2half_rn(t[x][y + i]);
    }
}

// ---------------- all layers' Wout [2048,768] -> woutT [768,2048] ----------------
__global__ void transpose_wout_all(const float* __restrict__ Wout, __half* __restrict__ dst)
{
    __shared__ float t[32][33];
    const int layer = blockIdx.z;
    const float* src = Wout + (size_t)layer * DFFV * DIMV;
    __half* d = dst + (size_t)layer * WT_LAYER + 4 * 589824 + 3145728;
    const int c0 = blockIdx.x * 32, r0 = blockIdx.y * 32;
    const int x = threadIdx.x, y = threadIdx.y;
    #pragma unroll
    for (int i = 0; i < 32; i += 8)
        t[y + i][x] = src[(size_t)(r0 + y + i) * DIMV + c0 + x];
    __syncthreads();
    #pragma unroll
    for (int i = 0; i < 32; i += 8)
        d[(size_t)(c0 + y + i) * DFFV + r0 + x] = __float2half_rn(t[x][y + i]);
}

// ---------------- all layers' Wmix/Wg -> wsm  +  bias permute ----------------
// grid = 40*DEPTHN; per layer: blocks 0..23 wsm rows, 24..39 bperm chunks.
__global__ void layerprep_all(const float* __restrict__ Wmix,
                              const float* __restrict__ Wg,
                              float* __restrict__ wsm,
                              const float* __restrict__ b,
                              float* __restrict__ bperm)
{
    const int layer = blockIdx.x / 40;
    const int j = blockIdx.x % 40;
    if (j < 2 * HEADSN) {
        const float* src = ((j < HEADSN) ? Wmix : Wg) + (size_t)layer * DIMV * HEADSN;
        const int col = (j < HEADSN) ? j : (j - HEADSN);
        float* w = wsm + (size_t)layer * 2 * HEADSN * DIMV;
        for (int c = threadIdx.x; c < DIMV; c += 256)
            w[(size_t)j * DIMV + c] = src[(size_t)c * HEADSN + col];
    } else {
        const int n = (j - 2 * HEADSN) * 256 + threadIdx.x;
        const int p = n >> 1, s = n & 1;
        bperm[(size_t)layer * 2 * DFFV + n] = b[(size_t)layer * 2 * DFFV + p + s * DFFV];
    }
}

// ---------------- rmsnorm: 192 threads/row, float4 vectorized ----------------
__global__ void rmsnorm_kernel(const float* __restrict__ in, const float* __restrict__ w,
                               void* __restrict__ out, int ashalf)
{
    __shared__ float red[6];
    __shared__ float snorm;
    const int row = blockIdx.x;
    const int tid = threadIdx.x;           // 192 threads, all active
    const float4 v = ((const float4*)(in + (size_t)row * DIMV))[tid];
    float ss = v.x * v.x + v.y * v.y + v.z * v.z + v.w * v.w;
    #pragma unroll
    for (int o = 16; o; o >>= 1) ss += __shfl_down_sync(0xffffffffu, ss, o);
    if ((tid & 31) == 0) red[tid >> 5] = ss;
    __syncthreads();
    if (tid == 0) {
        float t = 0.f;
        #pragma unroll
        for (int i = 0; i < 6; i++) t += red[i];
        snorm = rsqrtf(t / (float)DIMV + 1e-6f);
    }
    __syncthreads();
    const float sc = snorm;
    const float4 w4 = ((const float4*)w)[tid];
    const float o0 = v.x * sc * w4.x, o1 = v.y * sc * w4.y;
    const float o2 = v.z * sc * w4.z, o3 = v.w * sc * w4.w;
    if (ashalf) {
        __half2 h0 = __floats2half2_rn(o0, o1);
        __half2 h1 = __floats2half2_rn(o2, o3);
        uint2 u;
        u.x = *(const unsigned int*)&h0;
        u.y = *(const unsigned int*)&h1;
        ((uint2*)((__half*)out + (size_t)row * DIMV))[tid] = u;
    } else {
        ((float4*)((float*)out + (size_t)row * DIMV))[tid] = make_float4(o0, o1, o2, o3);
    }
}

// ============================================================================
// fp16 mma.sync GEMM (fp32 accumulate) — R14 config (best measured).
// 128x128 CTA tile, 4 warps (2x2), 64x64 warp tile, m16n8k16, ldmatrix.x4,
// BK=32, 3-stage cp.async, one __syncthreads per k-tile, 2 CTAs/SM.
// mode 0: fp32 out (+bias)(+res); mode 1: geglu half out; mode 2: plain half out.
// ============================================================================
#define HROW 40
#define T_TILE_H (128 * HROW)
#define STG_BYTES (2 * T_TILE_H * 2)            // 20480 B
#define GEMM_SMEM (3 * STG_BYTES)               // 61440 B

__global__ void __launch_bounds__(128) gemm_fp16_kernel(
    const __half* __restrict__ A, const __half* __restrict__ Bt,
    void* __restrict__ Cv, const float* __restrict__ bias,
    const float* __restrict__ res, int M, int N, int K, int mode)
{
    extern __shared__ __half smh[];
    const uint32_t smbase = (uint32_t)__cvta_generic_to_shared(smh);
    const int tid = threadIdx.x;
    const int bx = blockIdx.x, by = blockIdx.y;
    const int warp = tid >> 5, lane = tid & 31;
    const int wrow = warp >> 1, wcol = warp & 1;   // 2 x 2 warp grid
    const int grp = lane >> 2, qid = lane & 3;

    const int tL = lane >> 3, rL = lane & 7;
    const int arow = (tL & 1) * 8 + rL;
    const int acol = (tL >> 1) * 8;
    const int brow = (tL >> 1) * 8 + rL;
    const int bcol = (tL & 1) * 8;

    float acc[4][8][4];
    #pragma unroll
    for (int a = 0; a < 4; a++)
        #pragma unroll
        for (int b = 0; b < 8; b++)
            #pragma unroll
            for (int c = 0; c < 4; c++) acc[a][b][c] = 0.f;

    const int KT = K >> 5;
    const __half* Ab = A  + (size_t)(by * 128) * K;
    const __half* Bb = Bt + (size_t)(bx * 128) * K;

    auto loadTile = [&](int kt, int stg) {
        const uint32_t sA = smbase + stg * STG_BYTES;
        const uint32_t sB = sA + T_TILE_H * 2;
        const int k0 = kt * 32;
        #pragma unroll
        for (int i = 0; i < 4; i++) {
            int idx = tid + i * 128;
            int r = idx >> 2, c8 = (idx & 3) << 3;
            cp16(sA + (uint32_t)(r * HROW + c8) * 2, Ab + (size_t)r * K + k0 + c8);
            cp16(sB + (uint32_t)(r * HROW + c8) * 2, Bb + (size_t)r * K + k0 + c8);
        }
        asm volatile("cp.async.commit_group;");
    };

    auto computeTile = [&](int stg) {
        const uint32_t sA = smbase + stg * STG_BYTES;
        const uint32_t sB = sA + T_TILE_H * 2;
        #pragma unroll
        for (int kk = 0; kk < 2; kk++) {
            const int kb0 = kk * 16;
            uint32_t af[4][4], bf[8][2];
            #pragma unroll
            for (int mt = 0; mt < 4; mt++) {
                const uint32_t a_ad = sA +
                    (uint32_t)((wrow * 64 + mt * 16 + arow) * HROW + kb0 + acol) * 2;
                asm volatile(
                    "ldmatrix.sync.aligned.m8n8.x4.shared.b16 {%0,%1,%2,%3}, [%4];"
                    : "=r"(af[mt][0]), "=r"(af[mt][1]), "=r"(af[mt][2]), "=r"(af[mt][3])
                    : "r"(a_ad));
            }
            #pragma unroll
            for (int nt2 = 0; nt2 < 4; nt2++) {
                const uint32_t b_ad = sB +
                    (uint32_t)((wcol * 64 + nt2 * 16 + brow) * HROW + kb0 + bcol) * 2;
                asm volatile(
                    "ldmatrix.sync.aligned.m8n8.x4.shared.b16 {%0,%1,%2,%3}, [%4];"
                    : "=r"(bf[2*nt2][0]), "=r"(bf[2*nt2][1]),
                      "=r"(bf[2*nt2+1][0]), "=r"(bf[2*nt2+1][1])
                    : "r"(b_ad));
            }
            #pragma unroll
            for (int mt = 0; mt < 4; mt++)
                #pragma unroll
                for (int nt = 0; nt < 8; nt++)
                    asm volatile(
                        "mma.sync.aligned.m16n8k16.row.col.f32.f16.f16.f32 "
                        "{%0,%1,%2,%3}, {%4,%5,%6,%7}, {%8,%9}, {%0,%1,%2,%3};"
                        : "+f"(acc[mt][nt][0]), "+f"(acc[mt][nt][1]),
                          "+f"(acc[mt][nt][2]), "+f"(acc[mt][nt][3])
                        : "r"(af[mt][0]), "r"(af[mt][1]), "r"(af[mt][2]), "r"(af[mt][3]),
                          "r"(bf[nt][0]), "r"(bf[nt][1]));
        }
    };

    loadTile(0, 0);
    loadTile(1, 1);
    for (int kt = 0; kt < KT; kt++) {
        if (kt == KT - 1) asm volatile("cp.async.wait_group 0;");
        else              asm volatile("cp.async.wait_group 1;");
        __syncthreads();
        if (kt + 2 < KT) loadTile(kt + 2, (kt + 2) % 3);
        computeTile(kt % 3);
    }

    if (mode == 0) {
        float* C = (float*)Cv;
        #pragma unroll
        for (int mt = 0; mt < 4; mt++) {
            #pragma unroll
            for (int nt = 0; nt < 8; nt++) {
                const int r0 = by * 128 + wrow * 64 + mt * 16 + grp;
                const int c0 = bx * 128 + wcol * 64 + nt * 8 + qid * 2;
                float v0 = acc[mt][nt][0], v1 = acc[mt][nt][1];
                float v2 = acc[mt][nt][2], v3 = acc[mt][nt][3];
                if (bias) {
                    const float b0 = bias[c0], b1 = bias[c0 + 1];
                    v0 += b0; v1 += b1; v2 += b0; v3 += b1;
                }
                if (res) {
                    const float2 ra = *(const float2*)(res + (size_t)r0 * N + c0);
                    const float2 rb = *(const float2*)(res + (size_t)(r0 + 8) * N + c0);
                    v0 += ra.x; v1 += ra.y; v2 += rb.x; v3 += rb.y;
                }
                *(float2*)(C + (size_t)r0 * N + c0)       = make_float2(v0, v1);
                *(float2*)(C + (size_t)(r0 + 8) * N + c0) = make_float2(v2, v3);
            }
        }
    } else if (mode == 1) {
        __half* C = (__half*)Cv;
        const int NOUT = N >> 1;
        #pragma unroll
        for (int mt = 0; mt < 4; mt++) {
            #pragma unroll
            for (int nt = 0; nt < 8; nt++) {
                const int r0 = by * 128 + wrow * 64 + mt * 16 + grp;
                const int c0 = bx * 128 + wcol * 64 + nt * 8 + qid * 2;
                float v0 = acc[mt][nt][0], v1 = acc[mt][nt][1];
                float v2 = acc[mt][nt][2], v3 = acc[mt][nt][3];
                if (bias) {
                    const float b0 = bias[c0], b1 = bias[c0 + 1];
                    v0 += b0; v1 += b1; v2 += b0; v3 += b1;
                }
                const float ge1 = 0.5f * v1 * (1.f + erff(v1 * 0.70710678118654752f));
                const float ge3 = 0.5f * v3 * (1.f + erff(v3 * 0.70710678118654752f));
                const int p = c0 >> 1;
                C[(size_t)r0 * NOUT + p]       = __float2half_rn(v0 * ge1);
                C[(size_t)(r0 + 8) * NOUT + p] = __float2half_rn(v2 * ge3);
            }
        }
    } else {
        __half* C = (__half*)Cv;
        #pragma unroll
        for (int mt = 0; mt < 4; mt++) {
            #pragma unroll
            for (int nt = 0; nt < 8; nt++) {
                const int r0 = by * 128 + wrow * 64 + mt * 16 + grp;
                const int c0 = bx * 128 + wcol * 64 + nt * 8 + qid * 2;
                *(__half2*)(C + (size_t)r0 * N + c0) =
                    __floats2half2_rn(acc[mt][nt][0], acc[mt][nt][1]);
                *(__half2*)(C + (size_t)(r0 + 8) * N + c0) =
                    __floats2half2_rn(acc[mt][nt][2], acc[mt][nt][3]);
            }
        }
    }
}

// ---------------- fused mix/gate projections + v-lerp + k-norm (qkv fp16) ----------------
__global__ void mixvk_kernel(const __half* __restrict__ tn,
    const float* __restrict__ Wsm, const float* __restrict__ bmix,
    __half* __restrict__ qkv, const float* __restrict__ rv,
    const float* __restrict__ kgam, float* __restrict__ gate)
{
    __shared__ float row[DIMV];
    __shared__ float smix[HEADSN];
    __shared__ float red[24];
    const int tok = blockIdx.x;
    const int tid = threadIdx.x;           // 0..767
    row[tid] = __half2float(tn[(size_t)tok * DIMV + tid]);
    __syncthreads();

    const int w = tid >> 5, lane = tid & 31;
    {
        const float* Wr = Wsm + (size_t)w * DIMV;
        float s = 0.f;
        for (int c = lane; c < DIMV; c += 32) s += row[c] * Wr[c];
        #pragma unroll
        for (int o = 16; o; o >>= 1) s += __shfl_down_sync(0xffffffffu, s, o);
        if (lane == 0) {
            if (w < HEADSN) {
                s += bmix[w];
                smix[w] = 1.f / (1.f + __expf(-s));
            } else {
                gate[tok * HEADSN + (w - HEADSN)] = 1.f / (1.f + __expf(-s));
            }
        }
    }
    __syncthreads();

    const int h = tid >> 6;
    const size_t base = (size_t)tok * QSTR;
    const float m = smix[h];
    const float vv = __half2float(qkv[base + 1536 + tid]);
    qkv[base + 1536 + tid] =
        __float2half_rn(vv + m * (rv[(size_t)tok * DIMV + tid] - vv));
    const float kk = __half2float(qkv[base + 768 + tid]);
    float ss = kk * kk;
    #pragma unroll
    for (int o = 16; o; o >>= 1) ss += __shfl_down_sync(0xffffffffu, ss, o);
    if ((tid & 31) == 0) red[tid >> 5] = ss;
    __syncthreads();
    float n = sqrtf(red[2 * h] + red[2 * h + 1]);
    n = fmaxf(n, 1e-12f);
    qkv[base + 768 + tid] = __float2half_rn((kk / n) * (kgam[tid] + 1.f) * 8.0f);
}

// ---------------- spatial attention: qkv fp16 in, fp32 smem compute ----------------
__global__ void __launch_bounds__(256) attn_spatial_kernel(
    const __half* __restrict__ qkv, const float* __restrict__ gate, __half* __restrict__ o)
{
    extern __shared__ float sm[];
    float* Ks = sm;                 // 256*64
    float* Vs = sm + 256 * 64;
    float* Qs = sm + 2 * 256 * 64;
    const int h  = blockIdx.x;
    const size_t tok0 = (size_t)blockIdx.y * 256;
    const int tid = threadIdx.x;

    #pragma unroll
    for (int it = 0; it < 16; it++) {
        const int idx = tid + it * 256;
        const int row = idx >> 4;
        const int d4  = idx & 15;
        const size_t g4 = (tok0 + row) * (QSTR / 4) + h * 16 + d4;   // uint2 units
        const uint2 uq = ((const uint2*)qkv)[g4];
        const uint2 uk = ((const uint2*)qkv)[g4 + 192];
        const uint2 uv = ((const uint2*)qkv)[g4 + 384];
        const float2 q0 = __half22float2(*(const __half2*)&uq.x);
        const float2 q1 = __half22float2(*(const __half2*)&uq.y);
        const float2 k0 = __half22float2(*(const __half2*)&uk.x);
        const float2 k1 = __half22float2(*(const __half2*)&uk.y);
        const float2 v0 = __half22float2(*(const __half2*)&uv.x);
        const float2 v1 = __half22float2(*(const __half2*)&uv.y);
        ((float4*)Qs)[row * 16 + d4] = make_float4(q0.x, q0.y, q1.x, q1.y);
        ((float4*)Ks)[row * 16 + d4] = make_float4(k0.x, k0.y, k1.x, k1.y);
        ((float4*)Vs)[row * 16 + d4] = make_float4(v0.x, v0.y, v1.x, v1.y);
    }
    __syncthreads();

    float4 qr4[16];
    #pragma unroll
    for (int d4 = 0; d4 < 16; d4++) qr4[d4] = ((const float4*)(Qs + tid * 64))[d4];

    float mx = -1e30f, sum = 0.f;
    float4 oc4[16];
    #pragma unroll
    for (int d4 = 0; d4 < 16; d4++) oc4[d4] = make_float4(0.f, 0.f, 0.f, 0.f);

    for (int j0 = 0; j0 < 256; j0 += 32) {
        float s[32];
        float cmax = -1e30f;
        #pragma unroll
        for (int jj = 0; jj < 32; jj++) {
            const float4* Kr = (const float4*)(Ks + (j0 + jj) * 64);
            float a = 0.f;
            #pragma unroll
            for (int d4 = 0; d4 < 16; d4++) {
                const float4 k4 = Kr[d4];
                a += qr4[d4].x * k4.x + qr4[d4].y * k4.y
                   + qr4[d4].z * k4.z + qr4[d4].w * k4.w;
            }
            a *= 0.125f;
            a = ftanh(a * 0.02f) * 50.f;
            s[jj] = a;
            cmax = fmaxf(cmax, a);
        }
        const float mnew = fmaxf(mx, cmax);
        const float scale = __expf(mx - mnew);
        sum *= scale;
        #pragma unroll
        for (int d4 = 0; d4 < 16; d4++) {
            oc4[d4].x *= scale; oc4[d4].y *= scale;
            oc4[d4].z *= scale; oc4[d4].w *= scale;
        }
        #pragma unroll
        for (int jj = 0; jj < 32; jj++) {
            const float p = __expf(s[jj] - mnew);
            sum += p;
            const float4* Vr = (const float4*)(Vs + (j0 + jj) * 64);
            #pragma unroll
            for (int d4 = 0; d4 < 16; d4++) {
                const float4 v4 = Vr[d4];
                oc4[d4].x += p * v4.x; oc4[d4].y += p * v4.y;
                oc4[d4].z += p * v4.z; oc4[d4].w += p * v4.w;
            }
        }
        mx = mnew;
    }
    const float inv = 1.f / sum;
    const float g = gate[(tok0 + tid) * HEADSN + h] * inv;
    __half* ob = o + (tok0 + tid) * DIMV + h * DHV;
    #pragma unroll
    for (int d4 = 0; d4 < 16; d4++) {
        __half2 h0 = __floats2half2_rn(oc4[d4].x * g, oc4[d4].y * g);
        __half2 h1 = __floats2half2_rn(oc4[d4].z * g, oc4[d4].w * g);
        uint2 u;
        u.x = *(const unsigned int*)&h0;
        u.y = *(const unsigned int*)&h1;
        ((uint2*)ob)[d4] = u;
    }
}

// ---------------- time attention: seq=32 causal + rotary (qkv fp16) ----------------
__global__ void attn_time_kernel(
    const __half* __restrict__ qkv, const float* __restrict__ gate, __half* __restrict__ o)
{
    __shared__ float Ks[32 * 64];
    __shared__ float Vs[32 * 64];
    const int h  = blockIdx.x;
    const int bs = blockIdx.y;
    const int b = bs >> 8, s = bs & 255;
    const int lane = threadIdx.x;
    const size_t tok = ((size_t)(b * 32 + lane) * 256 + s);
    const size_t base = tok * QSTR + h * DHV;

    float cr[32], sr[32];
    #pragma unroll
    for (int d = 0; d < 32; d++) {
        const float fr = (float)lane * __expf(-(float)d * 0.28782313662425572f);
        cr[d] = __cosf(fr); sr[d] = __sinf(fr);
    }

    {
        float kr[64];
        #pragma unroll
        for (int d = 0; d < 64; d++) {
            kr[d] = __half2float(qkv[base + 768 + d]);
            Vs[lane * 64 + d] = __half2float(qkv[base + 1536 + d]);
        }
        #pragma unroll
        for (int d = 0; d < 32; d++) {
            Ks[lane * 64 + d]      = kr[d]      * cr[d] - kr[d + 32] * sr[d];
            Ks[lane * 64 + d + 32] = kr[d + 32] * cr[d] + kr[d]      * sr[d];
        }
    }
    __syncwarp();

    float qr[64];
    {
        float qt[64];
        #pragma unroll
        for (int d = 0; d < 64; d++) qt[d] = __half2float(qkv[base + d]);
        #pragma unroll
        for (int d = 0; d < 32; d++) {
            qr[d]      = qt[d]      * cr[d] - qt[d + 32] * sr[d];
            qr[d + 32] = qt[d + 32] * cr[d] + qt[d]      * sr[d];
        }
    }

    float sc[32];
    float mx = -1e30f;
    #pragma unroll
    for (int j = 0; j < 32; j++) {
        float a;
        if (j <= lane) {
            a = 0.f;
            #pragma unroll
            for (int d = 0; d < 64; d++) a += qr[d] * Ks[j * 64 + d];
            a *= 0.125f;
            a = ftanh(a * 0.02f) * 50.f;
        } else {
            a = -1e30f;
        }
        sc[j] = a;
        mx = fmaxf(mx, a);
    }
    float sum = 0.f;
    #pragma unroll
    for (int j = 0; j < 32; j++) {
        float e = (j <= lane) ? __expf(sc[j] - mx) : 0.f;
        sc[j] = e; sum += e;
    }
    const float inv = 1.f / sum;

    float oc[64];
    #pragma unroll
    for (int d = 0; d < 64; d++) oc[d] = 0.f;
    #pragma unroll
    for (int j = 0; j < 32; j++) {
        const float p = sc[j] * inv;
        #pragma unroll
        for (int d = 0; d < 64; d++) oc[d] += p * Vs[j * 64 + d];
    }
    const float g = gate[tok * HEADSN + h];
    __half* ob = o + tok * DIMV + h * DHV;
    #pragma unroll
    for (int d = 0; d < 64; d++) ob[d] = __float2half_rn(oc[d] * g);
}

// ---------------- host orchestration ----------------
extern "C" void kernel_launch(void* const* d_in, const int* in_sizes, int n_in,
                              void* d_out, int out_size)
{
    const float* tokens       = (const float*)d_in[0];
    const float* attn_norm_w  = (const float*)d_in[1];
    const float* Wq           = (const float*)d_in[2];
    const float* Wk           = (const float*)d_in[3];
    const float* Wv           = (const float*)d_in[4];
    const float* Wo           = (const float*)d_in[5];
    const float* Wg           = (const float*)d_in[6];
    const float* Wmix         = (const float*)d_in[7];
    const float* bmix         = (const float*)d_in[8];
    const float* kgam         = (const float*)d_in[9];
    const float* ff_norm_w    = (const float*)d_in[10];
    const float* Win          = (const float*)d_in[11];
    const float* b_in         = (const float*)d_in[12];
    const float* Wout         = (const float*)d_in[13];
    const float* b_out        = (const float*)d_in[14];
    const float* vr_norm_w    = (const float*)d_in[15];
    const float* vr_W         = (const float*)d_in[16];
    const float* final_norm_w = (const float*)d_in[17];

    float *x, *rv, *gate, *bpermall, *wsmall;
    __half *tn, *o, *qkv, *hg, *wtall, *wvr;
    cudaGetSymbolAddress((void**)&x,       g_x);
    cudaGetSymbolAddress((void**)&tn,      g_tn);
    cudaGetSymbolAddress((void**)&rv,      g_rv);
    cudaGetSymbolAddress((void**)&o,       g_o);
    cudaGetSymbolAddress((void**)&qkv,     g_qkv);
    cudaGetSymbolAddress((void**)&hg,      g_hg);
    cudaGetSymbolAddress((void**)&gate,    g_gate);
    cudaGetSymbolAddress((void**)&wtall,   g_wtall);
    cudaGetSymbolAddress((void**)&wvr,     g_wvr);
    cudaGetSymbolAddress((void**)&wsmall,  g_wsmall);
    cudaGetSymbolAddress((void**)&bpermall, g_bpermall);

    const int SPATIAL_SMEM = 3 * 256 * 64 * 4;   // 192 KB
    cudaFuncSetAttribute(attn_spatial_kernel,
                         cudaFuncAttributeMaxDynamicSharedMemorySize, SPATIAL_SMEM);
    cudaFuncSetAttribute(gemm_fp16_kernel,
                         cudaFuncAttributeMaxDynamicSharedMemorySize, GEMM_SMEM);

    const dim3 tb(32, 8);
    auto GEMM = [&](const __half* A, const __half* Bt, void* Cc,
                    const float* bias, const float* res, int M, int N, int K, int mode) {
        gemm_fp16_kernel<<<dim3(N / 128, M / 128), 128, GEMM_SMEM>>>(A, Bt, Cc, bias, res, M, N, K, mode);
    };

    // ---- prologue: ALL weight prep in 5 big launches ----
    transpose_vr_kernel<<<dim3(24, 24), tb>>>(vr_W, wvr);
    transpose_qkvo_all<<<dim3(24, 24, 4 * DEPTHN), tb>>>(Wq, Wk, Wv, Wo, wtall);
    transpose_ffw_all<<<dim3(128, 24, DEPTHN), tb>>>(Win, wtall);
    transpose_wout_all<<<dim3(24, 64, DEPTHN), tb>>>(Wout, wtall);
    layerprep_all<<<40 * DEPTHN, 256>>>(Wmix, Wg, wsmall, b_in, bpermall);

    // value residual from original tokens
    rmsnorm_kernel<<<NTOK, 192>>>(tokens, vr_norm_w, tn, 1);
    GEMM(tn, wvr, rv, nullptr, nullptr, NTOK, DIMV, DIMV, 0);

    const float* xcur = tokens;     // layer-0 residual source

    for (int i = 0; i < DEPTHN; i++) {
        const __half* wqkvT = wtall + (size_t)i * WT_LAYER;
        const __half* woT   = wqkvT + 3 * 589824;
        const __half* winT  = wqkvT + 4 * 589824;
        const __half* woutT = winT + 3145728;
        const float* wsm_i  = wsmall + (size_t)i * 2 * HEADSN * DIMV;
        const float* bperm_i = bpermall + (size_t)i * 2 * DFFV;
        const float* bmix_i = bmix + (size_t)i * HEADSN;
        const float* kgam_i = kgam + (size_t)i * HEADSN * DHV;
        const float* bout_i = b_out + (size_t)i * DIMV;

        // attention sublayer
        rmsnorm_kernel<<<NTOK, 192>>>(xcur, attn_norm_w + (size_t)i * DIMV, tn, 1);
        GEMM(tn, wqkvT, qkv, nullptr, nullptr, NTOK, QSTR, DIMV, 2);
        mixvk_kernel<<<NTOK, 768>>>(tn, wsm_i, bmix_i, qkv, rv, kgam_i, gate);

        if ((i + 1) % 4 == 0)
            attn_time_kernel<<<dim3(HEADSN, 512), 32>>>(qkv, gate, o);
        else
            attn_spatial_kernel<<<dim3(HEADSN, 64), 256, SPATIAL_SMEM>>>(qkv, gate, o);

        GEMM(o, woT, x, nullptr, xcur, NTOK, DIMV, DIMV, 0);
        xcur = x;

        // feedforward sublayer (geglu fused into FF1 epilogue)
        rmsnorm_kernel<<<NTOK, 192>>>(x, ff_norm_w + (size_t)i * DIMV, tn, 1);
        GEMM(tn, winT, hg, bperm_i, nullptr, NTOK, 2 * DFFV, DIMV, 1);
        GEMM(hg, woutT, x, bout_i, x, NTOK, DIMV, DFFV, 0);
    }

    rmsnorm_kernel<<<NTOK, 192>>>(x, final_norm_w, d_out, 0);
}